// round 8
// baseline (speedup 1.0000x reference)
#include <cuda_runtime.h>
#include <math.h>
#include <stdint.h>

#define B_ 32
#define L_ 256
#define A_ 20
#define NTHR 768            // 20 consumer warps + producer + 2 pair + const
#define TS 32               // tiles per stage
#define RING 2
#define NSTAGE 8            // 256 tiles / 32
#define STAGE_F 12800
#define STAGE_BYTES 51200

__device__ double g_res[L_][3];          // per-i {lse_sum, pair_sum, reg_sum}
__device__ unsigned int g_bcount = 0;    // reset by last block each launch

// smem layout (bytes):
//   0      .. 102400  ring data (2 x 51200), row-major tiles
//   102400 .. 110592  xpk uint32[8 sidx][32 b][8 w]: bytes 4*x[b][p]
//   110592 .. 110720  xi[32]
//   110720 .. 110800  wsrow[20]
//   110800 .. 110880  csts[20]
//   110880 .. 110976  sredr[24]
//   110976 .. 110984  pairv[2]
//   110984 .. 111016  mbarriers per r (stride 16): full +0, empty +8
//   111016 .. 111020  amLast
// epilogue reuse: lgbuf f32[32*21] @f0, dred double[4*32] @byte 4096
#define SMEM_BYTES 111024
#define MB_OFF 110984

__device__ __forceinline__ uint32_t smem_u32(const void* p) {
    uint32_t a;
    asm("{ .reg .u64 t; cvta.to.shared.u64 t, %1; cvt.u32.u64 %0, t; }" : "=r"(a) : "l"(p));
    return a;
}
#define MB_INIT(addr, cnt) \
    asm volatile("mbarrier.init.shared.b64 [%0], %1;" :: "r"(addr), "r"(cnt) : "memory")
#define MB_EXPECT_TX(addr, bytes) \
    asm volatile("mbarrier.arrive.expect_tx.shared.b64 _, [%0], %1;" :: "r"(addr), "r"(bytes) : "memory")
#define MB_ARRIVE(addr) \
    asm volatile("mbarrier.arrive.shared.b64 _, [%0];" :: "r"(addr) : "memory")

__device__ __forceinline__ void mb_wait_acq(uint32_t mbar, uint32_t parity) {
    asm volatile(
        "{\n\t.reg .pred P;\n\t"
        "WL_%=:\n\t"
        "mbarrier.try_wait.parity.acquire.cta.shared::cta.b64 P, [%0], %1, 0x989680;\n\t"
        "@P bra.uni WD_%=;\n\t"
        "bra.uni WL_%=;\n\t"
        "WD_%=:\n\t}"
        :: "r"(mbar), "r"(parity) : "memory");
}
__device__ __forceinline__ void mb_wait_rlx(uint32_t mbar, uint32_t parity) {
    asm volatile(
        "{\n\t.reg .pred P;\n\t"
        "WL_%=:\n\t"
        "mbarrier.try_wait.parity.relaxed.cta.shared::cta.b64 P, [%0], %1, 0x989680;\n\t"
        "@P bra.uni WD_%=;\n\t"
        "bra.uni WL_%=;\n\t"
        "WD_%=:\n\t}"
        :: "r"(mbar), "r"(parity) : "memory");
}
__device__ __forceinline__ void bulk_g2s(uint32_t dst, const void* src,
                                         uint32_t bytes, uint32_t mbar) {
    asm volatile(
        "cp.async.bulk.shared::cta.global.mbarrier::complete_tx::bytes [%0], [%1], %2, [%3];"
        :: "r"(dst), "l"(src), "r"(bytes), "r"(mbar) : "memory");
}

__global__ __launch_bounds__(NTHR, 2) void mrf_kernel(const int* __restrict__ x,
                                                      const float* __restrict__ ws,
                                                      const float* __restrict__ wp,
                                                      float* __restrict__ out) {
    extern __shared__ char smem_raw[];
    float*        bufs  = reinterpret_cast<float*>(smem_raw);
    uint32_t*     xpk   = reinterpret_cast<uint32_t*>(smem_raw + 102400);
    int*          xi    = reinterpret_cast<int*>(smem_raw + 110592);
    float*        wsrow = reinterpret_cast<float*>(smem_raw + 110720);
    float*        csts  = reinterpret_cast<float*>(smem_raw + 110800);
    float*        sredr = reinterpret_cast<float*>(smem_raw + 110880);
    float*        pairv = reinterpret_cast<float*>(smem_raw + 110976);
    int*          amLast= reinterpret_cast<int*>(smem_raw + 111016);
    const uint32_t mb0  = smem_u32(smem_raw + MB_OFF);
    const uint32_t bufa = smem_u32(smem_raw);

    const int i    = blockIdx.x;
    const int tid  = threadIdx.x;
    const int wid  = tid >> 5;
    const int lane = tid & 31;

    // full: tx-based (count 1). empty: 23 arrivals (20 consumers + 2 pair + const).
    if (tid == 0) {
        for (int r = 0; r < RING; r++) {
            MB_INIT(mb0 + r * 16, 1);
            MB_INIT(mb0 + r * 16 + 8, 23);
        }
    }

    // Pack x transpose, pre-scaled by 4:
    // xpk[sidx*256 + b*8 + w] = bytes 4*x[b][p], p = sidx*32 + 4w .. +3
    const int4* x4 = reinterpret_cast<const int4*>(x);
    for (int n = tid; n < 2048; n += NTHR) {
        int sidx = n >> 8, rem = n & 255;
        int b = rem >> 3, w = rem & 7;
        int4 q = x4[b * 64 + sidx * 8 + w];
        xpk[n] = (uint32_t)(q.x << 2) | ((uint32_t)(q.y << 2) << 8) |
                 ((uint32_t)(q.z << 2) << 16) | ((uint32_t)(q.w << 2) << 24);
    }
    if (tid < B_) xi[tid] = x[tid * L_ + i];
    if (tid >= 32 && tid < 52) wsrow[tid - 32] = ws[i * A_ + (tid - 32)];
    asm volatile("fence.proxy.async.shared::cta;" ::: "memory");
    __syncthreads();

    float accA = 0.f, accB = 0.f, pairA = 0.f, pairB = 0.f;
    float c_acc = 0.f, reg1 = 0.f, reg2 = 0.f;

    if (wid < 20) {
        // ---- Consumers: warp = j, lane = b; gather p>i + reg pass ----
        const char* btj0 = smem_raw + wid * 80;
        const uint4* xpk4 = reinterpret_cast<const uint4*>(xpk);
        const float4* b4all = reinterpret_cast<const float4*>(smem_raw);
        int r = 0, ph = 0;
        for (int sidx = 0; sidx < NSTAGE; sidx++) {
            mb_wait_acq(mb0 + r * 16, ph);

            // reg pass: 20 floats/lane (5 x LDS.128)
#pragma unroll
            for (int w = 0; w < 5; w++) {
                float4 q = b4all[r * 3200 + tid + w * 640];
                reg1 += fabsf(q.x); reg2 = fmaf(q.x, q.x, reg2);
                reg1 += fabsf(q.y); reg2 = fmaf(q.y, q.y, reg2);
                reg1 += fabsf(q.z); reg2 = fmaf(q.z, q.z, reg2);
                reg1 += fabsf(q.w); reg2 = fmaf(q.w, q.w, reg2);
            }

            const int pbase = sidx * TS;
            if (pbase + TS - 1 > i) {
                const char* btj = btj0 + r * STAGE_BYTES;
                const uint4 ua = xpk4[(sidx * 32 + lane) * 2];
                const uint4 ub = xpk4[(sidx * 32 + lane) * 2 + 1];
                const uint32_t wv[8] = {ua.x, ua.y, ua.z, ua.w, ub.x, ub.y, ub.z, ub.w};
                if (pbase > i) {          // ABOVE: all 32 tiles
#pragma unroll
                    for (int k = 0; k < TS; k++) {
                        uint32_t e4 = __byte_perm(wv[k >> 2], 0, 0x4440 | (k & 3));
                        float v = *reinterpret_cast<const float*>(btj + k * 1600 + e4);
                        if (k & 1) accB += v; else accA += v;
                    }
                } else {                  // MIXED
#pragma unroll
                    for (int k = 0; k < TS; k++) {
                        uint32_t e4 = __byte_perm(wv[k >> 2], 0, 0x4440 | (k & 3));
                        if (pbase + k > i) {
                            float v = *reinterpret_cast<const float*>(btj + k * 1600 + e4);
                            if (k & 1) accB += v; else accA += v;
                        }
                    }
                }
            }
            if (lane == 0) MB_ARRIVE(mb0 + r * 16 + 8);
            if (++r == RING) { r = 0; ph ^= 1; }
        }
    } else if (wid == 20) {
        // ---- Producer (lane 0) ----
        if (lane == 0) {
            const char* src = reinterpret_cast<const char*>(wp) + (size_t)i * 409600;
            int r = 0, wr = 0, wph = 0;
            for (int sidx = 0; sidx < NSTAGE; sidx++) {
                if (sidx >= RING) {
                    mb_wait_rlx(mb0 + wr * 16 + 8, wph);
                    if (++wr == RING) { wr = 0; wph ^= 1; }
                }
                MB_EXPECT_TX(mb0 + r * 16, STAGE_BYTES);
                bulk_g2s(bufa + r * STAGE_BYTES, src + (size_t)sidx * STAGE_BYTES,
                         STAGE_BYTES, mb0 + r * 16);
                if (++r == RING) r = 0;
            }
        }
    } else if (wid == 21 || wid == 22) {
        // ---- Pair warps: lane = b; warp 21 tiles 0-15, warp 22 tiles 16-31 ----
        const int koff = (wid == 22) ? 16 : 0;
        const char* bt0 = smem_raw + xi[lane] * 80 + koff * 1600;
        const uint4* xpk4 = reinterpret_cast<const uint4*>(xpk);
        int r = 0, ph = 0;
        for (int sidx = 0; sidx < NSTAGE; sidx++) {
            mb_wait_acq(mb0 + r * 16, ph);
            const char* bt = bt0 + r * STAGE_BYTES;
            const uint4 u = xpk4[(sidx * 32 + lane) * 2 + (koff >> 4)];
            const uint32_t wv[4] = {u.x, u.y, u.z, u.w};
#pragma unroll
            for (int k = 0; k < 16; k++) {
                uint32_t e4 = __byte_perm(wv[k >> 2], 0, 0x4440 | (k & 3));
                float v = *reinterpret_cast<const float*>(bt + k * 1600 + e4);
                if (k & 1) pairB += v; else pairA += v;
            }
            if (lane == 0) MB_ARRIVE(mb0 + r * 16 + 8);
            if (++r == RING) { r = 0; ph ^= 1; }
        }
    } else {
        // ---- Const warp (23): lanes 0..19, j = lane ----
        const int j20 = lane * 20;
        int r = 0, ph = 0;
        for (int sidx = 0; sidx < NSTAGE; sidx++) {
            mb_wait_acq(mb0 + r * 16, ph);
            const int pbase = sidx * TS;
            if (lane < 20 && pbase <= i) {
                const float* bt = bufs + r * STAGE_F;
                int tmax = i - pbase;              // t < tmax  <=>  p < i
                int lim = tmax < TS ? tmax : TS;
                for (int t = 0; t < lim; t++) c_acc += bt[t * 400 + j20 + 19];
                if (tmax < TS) c_acc += bt[tmax * 400 + j20 + lane];   // diag p==i
            }
            if (lane == 0) MB_ARRIVE(mb0 + r * 16 + 8);
            if (++r == RING) { r = 0; ph ^= 1; }
        }
    }

    // ---------------- Epilogue ----------------
    if (wid == 23 && lane < 20) csts[lane] = c_acc;
    if (wid < 20) {
        float rv = reg1 + reg2;
#pragma unroll
        for (int o = 16; o > 0; o >>= 1) rv += __shfl_down_sync(0xffffffffu, rv, o);
        if (lane == 0) sredr[wid] = rv;
    }
    if (wid == 21 || wid == 22) {
        float pv = pairA + pairB;
#pragma unroll
        for (int o = 16; o > 0; o >>= 1) pv += __shfl_down_sync(0xffffffffu, pv, o);
        if (lane == 0) pairv[wid - 21] = pv;
    }
    __syncthreads();

    if (wid < 20) bufs[lane * 21 + wid] = accA + accB + csts[wid] + wsrow[wid];
    if (tid == 736) g_res[i][1] = (double)pairv[0] + (double)pairv[1];
    __syncthreads();

    if (tid < 32) {       // lse per b, minus single
        const float* row = &bufs[tid * 21];
        float m = row[0];
#pragma unroll
        for (int j = 1; j < A_; j++) m = fmaxf(m, row[j]);
        float se = 0.f;
#pragma unroll
        for (int j = 0; j < A_; j++) se += __expf(row[j] - m);
        float lse = m + __logf(se);
        double val = (double)lse - (double)wsrow[xi[tid]];
#pragma unroll
        for (int o = 16; o > 0; o >>= 1) val += __shfl_down_sync(0xffffffffu, val, o);
        if (tid == 0) g_res[i][0] = val;
    } else if (tid < 64) {   // reg sum over 20 warps
        double rv = (lane < 20) ? (double)sredr[lane] : 0.0;
#pragma unroll
        for (int o = 16; o > 0; o >>= 1) rv += __shfl_down_sync(0xffffffffu, rv, o);
        if (lane == 0) g_res[i][2] = rv;
    }
    __syncthreads();

    // ---------------- Fused deterministic final reduction (last CTA) ----------------
    if (tid == 0) {
        __threadfence();
        *amLast = (atomicAdd(&g_bcount, 1u) == (unsigned)(gridDim.x - 1)) ? 1 : 0;
    }
    __syncthreads();
    if (!*amLast) return;
    __threadfence();

    double LS = 0.0, PA = 0.0, RP = 0.0, RS = 0.0;
    if (tid < L_) { LS = g_res[tid][0]; PA = g_res[tid][1]; RP = g_res[tid][2]; }
    for (int n = tid; n < L_ * A_; n += NTHR) {
        float w = ws[n];
        RS += (double)fabsf(w) + (double)w * (double)w;
    }
    double* dred = reinterpret_cast<double*>(smem_raw + 4096);
#pragma unroll
    for (int o = 16; o > 0; o >>= 1) {
        LS += __shfl_down_sync(0xffffffffu, LS, o);
        PA += __shfl_down_sync(0xffffffffu, PA, o);
        RP += __shfl_down_sync(0xffffffffu, RP, o);
        RS += __shfl_down_sync(0xffffffffu, RS, o);
    }
    if (lane == 0) {
        dred[wid] = LS; dred[32 + wid] = PA; dred[64 + wid] = RP; dred[96 + wid] = RS;
    }
    __syncthreads();
    if (tid == 0) {
        double ls = 0, pa = 0, rp = 0, rs = 0;
        for (int w = 0; w < 24; w++) {
            ls += dred[w]; pa += dred[32 + w]; rp += dred[64 + w]; rs += dred[96 + w];
        }
        // LAMBDA_SINGLE = 1.0, LAMBDA_PAIR = 0.2*(L-1) = 51.0
        out[0] = (float)((ls - pa) / (double)B_ + 1.0 * rs + 51.0 * rp);
        g_bcount = 0;   // self-reset for graph replay
    }
}

extern "C" void kernel_launch(void* const* d_in, const int* in_sizes, int n_in,
                              void* d_out, int out_size) {
    (void)in_sizes; (void)n_in; (void)out_size;
    const int*   x  = (const int*)d_in[0];
    const float* ws = (const float*)d_in[1];
    const float* wp = (const float*)d_in[2];
    float* out = (float*)d_out;

    cudaFuncSetAttribute(mrf_kernel, cudaFuncAttributeMaxDynamicSharedMemorySize, SMEM_BYTES);
    mrf_kernel<<<L_, NTHR, SMEM_BYTES>>>(x, ws, wp, out);
}